// round 2
// baseline (speedup 1.0000x reference)
#include <cuda_runtime.h>
#include <cuda_bf16.h>
#include <math.h>

// ---------------------------------------------------------------------------
// MultiHeadAttention: out = proj_o( softmax(Q Kᵀ/√dk) V ),  fp32 end-to-end.
// Shapes: S=4096, D_MODEL=1024, H=16, DK=64, B=1.
// Inputs (metadata order): q,k,v, Wq,bq, Wk,bk, Wv,bv, Wo,bo
// ---------------------------------------------------------------------------

#define S_LEN   4096
#define DMODEL  1024
#define NHEAD   16
#define DK      64

// Scratch (device globals — no allocations allowed)
__device__ float g_Q[S_LEN * DMODEL];
__device__ float g_K[S_LEN * DMODEL];
__device__ float g_V[S_LEN * DMODEL];
__device__ float g_C[S_LEN * DMODEL];

// ---------------------------------------------------------------------------
// SGEMM: C[M,N] = A[M,K] * W[N,K]^T + bias[N]   (both operands K-major)
// 128x128 block tile, BK=8, 256 threads, 8x8 per-thread tile.
// ---------------------------------------------------------------------------
#define BM 128
#define BN 128
#define BK 8

__global__ __launch_bounds__(256, 2)
void sgemm_bias(const float* __restrict__ A, const float* __restrict__ W,
                const float* __restrict__ bias, float* __restrict__ C,
                int M, int N, int K)
{
    __shared__ float As[BK][BM];
    __shared__ float Bs[BK][BN];

    const int tid = threadIdx.x;          // 0..255
    const int tx  = tid & 15;             // 0..15
    const int ty  = tid >> 4;             // 0..15
    const int rowBase = blockIdx.y * BM;
    const int colBase = blockIdx.x * BN;

    // load mapping: 256 threads, each loads one float4 of A tile and one of W tile
    const int lrow = tid >> 1;            // 0..127
    const int lk4  = (tid & 1) * 4;       // 0 or 4

    float acc[8][8];
    #pragma unroll
    for (int i = 0; i < 8; i++)
        #pragma unroll
        for (int j = 0; j < 8; j++) acc[i][j] = 0.f;

    const float* Aptr = A + (size_t)(rowBase + lrow) * K + lk4;
    const float* Wptr = W + (size_t)(colBase + lrow) * K + lk4;

    for (int k0 = 0; k0 < K; k0 += BK) {
        float4 a4 = *(const float4*)(Aptr + k0);
        float4 b4 = *(const float4*)(Wptr + k0);
        __syncthreads();
        As[lk4 + 0][lrow] = a4.x; As[lk4 + 1][lrow] = a4.y;
        As[lk4 + 2][lrow] = a4.z; As[lk4 + 3][lrow] = a4.w;
        Bs[lk4 + 0][lrow] = b4.x; Bs[lk4 + 1][lrow] = b4.y;
        Bs[lk4 + 2][lrow] = b4.z; Bs[lk4 + 3][lrow] = b4.w;
        __syncthreads();

        #pragma unroll
        for (int k = 0; k < BK; k++) {
            float af[8], bf[8];
            *(float4*)(af + 0) = *(const float4*)(&As[k][ty * 8 + 0]);
            *(float4*)(af + 4) = *(const float4*)(&As[k][ty * 8 + 4]);
            *(float4*)(bf + 0) = *(const float4*)(&Bs[k][tx * 8 + 0]);
            *(float4*)(bf + 4) = *(const float4*)(&Bs[k][tx * 8 + 4]);
            #pragma unroll
            for (int i = 0; i < 8; i++)
                #pragma unroll
                for (int j = 0; j < 8; j++)
                    acc[i][j] = fmaf(af[i], bf[j], acc[i][j]);
        }
    }

    #pragma unroll
    for (int i = 0; i < 8; i++) {
        const int r = rowBase + ty * 8 + i;
        #pragma unroll
        for (int j = 0; j < 8; j += 4) {
            const int c = colBase + tx * 8 + j;
            float4 o;
            o.x = acc[i][j + 0] + bias[c + 0];
            o.y = acc[i][j + 1] + bias[c + 1];
            o.z = acc[i][j + 2] + bias[c + 2];
            o.w = acc[i][j + 3] + bias[c + 3];
            *(float4*)(C + (size_t)r * N + c) = o;
        }
    }
}

// ---------------------------------------------------------------------------
// Flash attention (fp32): Br=Bc=64, Dk=64, 256 threads.
// Thread (tx,ty) in 16x16 grid owns a 4x4 fragment:
//   rows ty*4..+3 (query rows) x cols tx*4..+3 (key cols for S; head-dims for O)
// ---------------------------------------------------------------------------
#define BR 64
#define BC 64
#define QP 65   // Qs pitch
#define KP 65   // Ks pitch
#define VP 68   // Vs pitch (float4-aligned)
#define PP 65   // Ps pitch

__global__ __launch_bounds__(256, 2)
void flash_attn(const float* __restrict__ Q, const float* __restrict__ K,
                const float* __restrict__ V, float* __restrict__ O)
{
    extern __shared__ float sm[];
    float* Qs = sm;                    // BR x QP
    float* Ks = Qs + BR * QP;          // BC x KP
    float* Vs = Ks + BC * KP;          // BC x VP
    float* Ps = Vs + BC * VP;          // BR x PP

    const int h     = blockIdx.y;
    const int qBase = blockIdx.x * BR;
    const int tid   = threadIdx.x;
    const int tx    = tid & 15;
    const int ty    = tid >> 4;
    const size_t hoff = (size_t)h * DK;

    // load Q tile [BR x DK] (pitch QP, scalar stores)
    for (int i = tid; i < BR * (DK / 4); i += 256) {
        const int r  = i >> 4;
        const int d4 = (i & 15) * 4;
        float4 v = *(const float4*)(Q + (size_t)(qBase + r) * DMODEL + hoff + d4);
        Qs[r * QP + d4 + 0] = v.x; Qs[r * QP + d4 + 1] = v.y;
        Qs[r * QP + d4 + 2] = v.z; Qs[r * QP + d4 + 3] = v.w;
    }

    float m_i[4], l_i[4], o_acc[4][4];
    #pragma unroll
    for (int i = 0; i < 4; i++) {
        m_i[i] = -INFINITY; l_i[i] = 0.f;
        #pragma unroll
        for (int j = 0; j < 4; j++) o_acc[i][j] = 0.f;
    }

    const float scale = 0.125f;  // 1/sqrt(64)

    for (int c0 = 0; c0 < S_LEN; c0 += BC) {
        __syncthreads();   // previous PV GEMM done before overwriting K/V
        for (int i = tid; i < BC * (DK / 4); i += 256) {
            const int r  = i >> 4;
            const int d4 = (i & 15) * 4;
            float4 kv = *(const float4*)(K + (size_t)(c0 + r) * DMODEL + hoff + d4);
            Ks[r * KP + d4 + 0] = kv.x; Ks[r * KP + d4 + 1] = kv.y;
            Ks[r * KP + d4 + 2] = kv.z; Ks[r * KP + d4 + 3] = kv.w;
            float4 vv = *(const float4*)(V + (size_t)(c0 + r) * DMODEL + hoff + d4);
            *(float4*)(Vs + r * VP + d4) = vv;
        }
        __syncthreads();

        // ---- S = Q Kᵀ (register-blocked) ----
        float Sf[4][4];
        #pragma unroll
        for (int i = 0; i < 4; i++)
            #pragma unroll
            for (int j = 0; j < 4; j++) Sf[i][j] = 0.f;

        #pragma unroll 8
        for (int d = 0; d < DK; d++) {
            float qf[4], kf[4];
            #pragma unroll
            for (int i = 0; i < 4; i++) qf[i] = Qs[(ty * 4 + i) * QP + d];
            #pragma unroll
            for (int j = 0; j < 4; j++) kf[j] = Ks[(tx * 4 + j) * KP + d];
            #pragma unroll
            for (int i = 0; i < 4; i++)
                #pragma unroll
                for (int j = 0; j < 4; j++)
                    Sf[i][j] = fmaf(qf[i], kf[j], Sf[i][j]);
        }

        // ---- online softmax (row reductions across 16 lanes) ----
        #pragma unroll
        for (int i = 0; i < 4; i++) {
            float mx = fmaxf(fmaxf(Sf[i][0], Sf[i][1]), fmaxf(Sf[i][2], Sf[i][3])) * scale;
            #pragma unroll
            for (int off = 8; off >= 1; off >>= 1)
                mx = fmaxf(mx, __shfl_xor_sync(0xffffffffu, mx, off));
            const float m_new = fmaxf(m_i[i], mx);
            const float corr  = __expf(m_i[i] - m_new);
            float rs = 0.f;
            #pragma unroll
            for (int j = 0; j < 4; j++) {
                const float p = __expf(fmaf(Sf[i][j], scale, -m_new));
                Sf[i][j] = p;
                rs += p;
            }
            #pragma unroll
            for (int off = 8; off >= 1; off >>= 1)
                rs += __shfl_xor_sync(0xffffffffu, rs, off);
            l_i[i] = l_i[i] * corr + rs;
            m_i[i] = m_new;
            #pragma unroll
            for (int j = 0; j < 4; j++) o_acc[i][j] *= corr;
            // stage P to smem
            #pragma unroll
            for (int j = 0; j < 4; j++)
                Ps[(ty * 4 + i) * PP + tx * 4 + j] = Sf[i][j];
        }
        __syncthreads();

        // ---- O += P V ----
        #pragma unroll 8
        for (int c = 0; c < BC; c++) {
            float pf[4];
            #pragma unroll
            for (int i = 0; i < 4; i++) pf[i] = Ps[(ty * 4 + i) * PP + c];
            const float4 vf = *(const float4*)(Vs + c * VP + tx * 4);
            #pragma unroll
            for (int i = 0; i < 4; i++) {
                o_acc[i][0] = fmaf(pf[i], vf.x, o_acc[i][0]);
                o_acc[i][1] = fmaf(pf[i], vf.y, o_acc[i][1]);
                o_acc[i][2] = fmaf(pf[i], vf.z, o_acc[i][2]);
                o_acc[i][3] = fmaf(pf[i], vf.w, o_acc[i][3]);
            }
        }
    }

    // ---- epilogue: normalize + store ----
    #pragma unroll
    for (int i = 0; i < 4; i++) {
        const float inv_l = 1.f / l_i[i];
        float4 o;
        o.x = o_acc[i][0] * inv_l; o.y = o_acc[i][1] * inv_l;
        o.z = o_acc[i][2] * inv_l; o.w = o_acc[i][3] * inv_l;
        *(float4*)(O + (size_t)(qBase + ty * 4 + i) * DMODEL + hoff + tx * 4) = o;
    }
}

// ---------------------------------------------------------------------------
extern "C" void kernel_launch(void* const* d_in, const int* in_sizes, int n_in,
                              void* d_out, int out_size)
{
    const float* q  = (const float*)d_in[0];
    const float* k  = (const float*)d_in[1];
    const float* v  = (const float*)d_in[2];
    const float* Wq = (const float*)d_in[3];
    const float* bq = (const float*)d_in[4];
    const float* Wk = (const float*)d_in[5];
    const float* bk = (const float*)d_in[6];
    const float* Wv = (const float*)d_in[7];
    const float* bv = (const float*)d_in[8];
    const float* Wo = (const float*)d_in[9];
    const float* bo = (const float*)d_in[10];
    float* out = (float*)d_out;

    float *gq, *gk, *gv, *gc;
    cudaGetSymbolAddress((void**)&gq, g_Q);
    cudaGetSymbolAddress((void**)&gk, g_K);
    cudaGetSymbolAddress((void**)&gv, g_V);
    cudaGetSymbolAddress((void**)&gc, g_C);

    const int smem = (BR * QP + BC * KP + BC * VP + BR * PP) * (int)sizeof(float);
    cudaFuncSetAttribute(flash_attn, cudaFuncAttributeMaxDynamicSharedMemorySize, smem);

    dim3 gGemm(DMODEL / BN, S_LEN / BM);   // (8, 32)
    sgemm_bias<<<gGemm, 256>>>(q, Wq, bq, gq, S_LEN, DMODEL, DMODEL);
    sgemm_bias<<<gGemm, 256>>>(k, Wk, bk, gk, S_LEN, DMODEL, DMODEL);
    sgemm_bias<<<gGemm, 256>>>(v, Wv, bv, gv, S_LEN, DMODEL, DMODEL);

    dim3 gAttn(S_LEN / BR, NHEAD);         // (64, 16)
    flash_attn<<<gAttn, 256, smem>>>(gq, gk, gv, gc);

    sgemm_bias<<<gGemm, 256>>>(gc, Wo, bo, out, S_LEN, DMODEL, DMODEL);
}

// round 3
// speedup vs baseline: 2.8764x; 2.8764x over previous
#include <cuda_runtime.h>
#include <cuda_bf16.h>
#include <math.h>

// ---------------------------------------------------------------------------
// MultiHeadAttention via bf16 split-precision tensor cores (mma.sync m16n8k16).
// Every operand split x = hi + lo (bf16); each GEMM computes
//   hi*hi + lo*hi + hi*lo  (fp32 accumulate)  -> ~fp32 accuracy (eps ~ 2^-18).
// ---------------------------------------------------------------------------

#define S_LEN  4096
#define DMODEL 1024
#define NHEAD  16
#define DK     64

typedef __nv_bfloat16  bf16;
typedef __nv_bfloat162 bf162;

#define SD (S_LEN * DMODEL)    // 4194304
#define DD (DMODEL * DMODEL)   // 1048576

// 14*SD + 8*DD = 67108864 elements = 128 MB scratch
__device__ bf16 g_buf[67108864];

// ---------------------------------------------------------------------------
// helpers
// ---------------------------------------------------------------------------
__device__ __forceinline__ unsigned saddr(const void* p) {
    return (unsigned)__cvta_generic_to_shared(p);
}

#define LDSM4(R, A)                                                            \
    asm volatile("ldmatrix.sync.aligned.m8n8.x4.shared.b16 {%0,%1,%2,%3}, [%4];" \
                 : "=r"((R)[0]), "=r"((R)[1]), "=r"((R)[2]), "=r"((R)[3])      \
                 : "r"(A))

#define LDSM4T(R, A)                                                           \
    asm volatile("ldmatrix.sync.aligned.m8n8.x4.trans.shared.b16 {%0,%1,%2,%3}, [%4];" \
                 : "=r"((R)[0]), "=r"((R)[1]), "=r"((R)[2]), "=r"((R)[3])      \
                 : "r"(A))

#define MMA_BF16(C, A, B0, B1)                                                 \
    asm volatile("mma.sync.aligned.m16n8k16.row.col.f32.bf16.bf16.f32 "        \
                 "{%0,%1,%2,%3}, {%4,%5,%6,%7}, {%8,%9}, {%0,%1,%2,%3};"       \
                 : "+f"((C)[0]), "+f"((C)[1]), "+f"((C)[2]), "+f"((C)[3])      \
                 : "r"((A)[0]), "r"((A)[1]), "r"((A)[2]), "r"((A)[3]),         \
                   "r"(B0), "r"(B1))

__device__ __forceinline__ void store_split(bf16* __restrict__ H, bf16* __restrict__ L,
                                            size_t idx, float a, float b)
{
    bf16 ha = __float2bfloat16_rn(a), hb = __float2bfloat16_rn(b);
    *(bf162*)&H[idx] = __halves2bfloat162(ha, hb);
    *(bf162*)&L[idx] = __floats2bfloat162_rn(a - __bfloat162float(ha),
                                             b - __bfloat162float(hb));
}

__device__ __forceinline__ void split_pack(float a, float b, unsigned& hi, unsigned& lo)
{
    bf16 ha = __float2bfloat16_rn(a), hb = __float2bfloat16_rn(b);
    bf162 hh = __halves2bfloat162(ha, hb);
    hi = *reinterpret_cast<unsigned*>(&hh);
    bf162 ll = __floats2bfloat162_rn(a - __bfloat162float(ha),
                                     b - __bfloat162float(hb));
    lo = *reinterpret_cast<unsigned*>(&ll);
}

// ---------------------------------------------------------------------------
// fp32 -> (hi, lo) bf16 split (elementwise)
// ---------------------------------------------------------------------------
__global__ void split_f32_kernel(const float* __restrict__ x,
                                 bf16* __restrict__ h, bf16* __restrict__ l, int n4)
{
    int idx = blockIdx.x * blockDim.x + threadIdx.x;
    if (idx >= n4) return;
    float4 v = ((const float4*)x)[idx];
    bf16 h0 = __float2bfloat16_rn(v.x), h1 = __float2bfloat16_rn(v.y);
    bf16 h2 = __float2bfloat16_rn(v.z), h3 = __float2bfloat16_rn(v.w);
    bf162* H = (bf162*)h;
    bf162* L = (bf162*)l;
    H[2 * idx]     = __halves2bfloat162(h0, h1);
    H[2 * idx + 1] = __halves2bfloat162(h2, h3);
    L[2 * idx]     = __floats2bfloat162_rn(v.x - __bfloat162float(h0),
                                           v.y - __bfloat162float(h1));
    L[2 * idx + 1] = __floats2bfloat162_rn(v.z - __bfloat162float(h2),
                                           v.w - __bfloat162float(h3));
}

// ---------------------------------------------------------------------------
// Split-bf16 GEMM: C[M,N] = A[M,K] * W[N,K]^T + bias
// 128x128 block, BK=16, 8 warps (4m x 2n), warp tile 32x64, double-buffered.
// Output: fp32 (Cf) or bf16 hi/lo pair (Coh/Col).
// smem: 2 buffers x 4 arrays x 128x24 bf16 = 49152 B
// ---------------------------------------------------------------------------
#define GP 24

__global__ __launch_bounds__(256, 2)
void gemm_bf16_split(const bf16* __restrict__ Ah, const bf16* __restrict__ Al,
                     const bf16* __restrict__ Bh, const bf16* __restrict__ Bl,
                     const float* __restrict__ bias,
                     float* __restrict__ Cf,
                     bf16* __restrict__ Coh, bf16* __restrict__ Col,
                     int M, int N, int K)
{
    extern __shared__ bf16 smg[];
    const int tid  = threadIdx.x;
    const int lane = tid & 31, wid = tid >> 5;
    const int g = lane >> 2, t = lane & 3;
    const int li = lane >> 3, lj = lane & 7;
    const int wm0 = (wid & 3) * 32;
    const int wn0 = (wid >> 2) * 64;
    const int rowBase = blockIdx.y * 128, colBase = blockIdx.x * 128;

    float acc[2][8][4];
    #pragma unroll
    for (int a = 0; a < 2; a++)
        #pragma unroll
        for (int b = 0; b < 8; b++)
            #pragma unroll
            for (int c = 0; c < 4; c++) acc[a][b][c] = 0.f;

    const int lrow = tid >> 1, lhalf = (tid & 1) * 8;
    const bf16* pAh = Ah + (size_t)(rowBase + lrow) * K + lhalf;
    const bf16* pAl = Al + (size_t)(rowBase + lrow) * K + lhalf;
    const bf16* pBh = Bh + (size_t)(colBase + lrow) * K + lhalf;
    const bf16* pBl = Bl + (size_t)(colBase + lrow) * K + lhalf;
    const int sts = lrow * GP + lhalf;

    uint4 rAh = *(const uint4*)pAh;
    uint4 rAl = *(const uint4*)pAl;
    uint4 rBh = *(const uint4*)pBh;
    uint4 rBl = *(const uint4*)pBl;
    *(uint4*)&smg[0 * 3072 + sts] = rAh;
    *(uint4*)&smg[1 * 3072 + sts] = rAl;
    *(uint4*)&smg[2 * 3072 + sts] = rBh;
    *(uint4*)&smg[3 * 3072 + sts] = rBl;
    __syncthreads();

    const int KS = K >> 4;
    for (int ks = 0; ks < KS; ks++) {
        const int cur = (ks & 1) * 12288;
        const bool hasNext = (ks + 1 < KS);
        if (hasNext) {
            const int k0 = (ks + 1) << 4;
            rAh = *(const uint4*)(pAh + k0);
            rAl = *(const uint4*)(pAl + k0);
            rBh = *(const uint4*)(pBh + k0);
            rBl = *(const uint4*)(pBl + k0);
        }
        unsigned afh[2][4], afl[2][4];
        #pragma unroll
        for (int mt = 0; mt < 2; mt++) {
            const int row = wm0 + mt * 16 + (li & 1) * 8 + lj;
            const int col = (li >> 1) * 8;
            LDSM4(afh[mt], saddr(&smg[cur + 0 * 3072 + row * GP + col]));
            LDSM4(afl[mt], saddr(&smg[cur + 1 * 3072 + row * GP + col]));
        }
        #pragma unroll
        for (int ntp = 0; ntp < 4; ntp++) {
            const int row = wn0 + ntp * 16 + (li >> 1) * 8 + lj;
            const int col = (li & 1) * 8;
            unsigned bh[4], bl[4];
            LDSM4(bh, saddr(&smg[cur + 2 * 3072 + row * GP + col]));
            LDSM4(bl, saddr(&smg[cur + 3 * 3072 + row * GP + col]));
            #pragma unroll
            for (int mt = 0; mt < 2; mt++) {
                MMA_BF16(acc[mt][2 * ntp],     afh[mt], bh[0], bh[1]);
                MMA_BF16(acc[mt][2 * ntp],     afl[mt], bh[0], bh[1]);
                MMA_BF16(acc[mt][2 * ntp],     afh[mt], bl[0], bl[1]);
                MMA_BF16(acc[mt][2 * ntp + 1], afh[mt], bh[2], bh[3]);
                MMA_BF16(acc[mt][2 * ntp + 1], afl[mt], bh[2], bh[3]);
                MMA_BF16(acc[mt][2 * ntp + 1], afh[mt], bl[2], bl[3]);
            }
        }
        if (hasNext) {
            const int nxt = ((ks + 1) & 1) * 12288;
            *(uint4*)&smg[nxt + 0 * 3072 + sts] = rAh;
            *(uint4*)&smg[nxt + 1 * 3072 + sts] = rAl;
            *(uint4*)&smg[nxt + 2 * 3072 + sts] = rBh;
            *(uint4*)&smg[nxt + 3 * 3072 + sts] = rBl;
        }
        __syncthreads();
    }

    // epilogue
    #pragma unroll
    for (int mt = 0; mt < 2; mt++) {
        const int r0 = rowBase + wm0 + mt * 16 + g;
        #pragma unroll
        for (int nt = 0; nt < 8; nt++) {
            const int c = colBase + wn0 + nt * 8 + 2 * t;
            const float b0 = bias[c], b1 = bias[c + 1];
            const float v00 = acc[mt][nt][0] + b0, v01 = acc[mt][nt][1] + b1;
            const float v10 = acc[mt][nt][2] + b0, v11 = acc[mt][nt][3] + b1;
            const size_t i0 = (size_t)r0 * N + c;
            const size_t i1 = (size_t)(r0 + 8) * N + c;
            if (Cf) {
                *(float2*)&Cf[i0] = make_float2(v00, v01);
                *(float2*)&Cf[i1] = make_float2(v10, v11);
            } else {
                store_split(Coh, Col, i0, v00, v01);
                store_split(Coh, Col, i1, v10, v11);
            }
        }
    }
}

// ---------------------------------------------------------------------------
// Split-bf16 flash attention: Br=128, Bc=64, Dk=64, 8 warps (16 rows each).
// QK^T and PV on tensor cores; softmax fp32; P built in-register from S frags.
// smem: Q(hi/lo) 128x72 + K,V(hi/lo) 64x72 = 73728 B
// ---------------------------------------------------------------------------
#define AP 72

__global__ __launch_bounds__(256, 2)
void attn_bf16_split(const bf16* __restrict__ Qh, const bf16* __restrict__ Ql,
                     const bf16* __restrict__ Kh, const bf16* __restrict__ Kl,
                     const bf16* __restrict__ Vh, const bf16* __restrict__ Vl,
                     bf16* __restrict__ Ch, bf16* __restrict__ Cl)
{
    extern __shared__ bf16 sma[];
    bf16* QHs = sma;            // 128*72 = 9216
    bf16* QLs = sma + 9216;
    bf16* KHs = sma + 18432;    // 64*72 = 4608
    bf16* KLs = sma + 23040;
    bf16* VHs = sma + 27648;
    bf16* VLs = sma + 32256;

    const int tid = threadIdx.x, lane = tid & 31, wid = tid >> 5;
    const int g = lane >> 2, t = lane & 3;
    const int li = lane >> 3, lj = lane & 7;
    const int h = blockIdx.y;
    const int qBase = blockIdx.x * 128;
    const int hoff = h * DK;
    const int m0 = wid * 16;

    // stage Q tile (hi/lo)
    #pragma unroll
    for (int p = 0; p < 4; p++) {
        const int c = tid + p * 256;
        const int r = c >> 3, off = (c & 7) * 8;
        const size_t gi = (size_t)(qBase + r) * DMODEL + hoff + off;
        *(uint4*)&QHs[r * AP + off] = *(const uint4*)&Qh[gi];
        *(uint4*)&QLs[r * AP + off] = *(const uint4*)&Ql[gi];
    }

    float Oa[8][4];
    #pragma unroll
    for (int a = 0; a < 8; a++)
        #pragma unroll
        for (int b = 0; b < 4; b++) Oa[a][b] = 0.f;
    float mrow0 = -1e30f, mrow1 = -1e30f, lrow0 = 0.f, lrow1 = 0.f;
    const float C1 = 0.125f;  // 1/sqrt(DK)

    for (int c0 = 0; c0 < S_LEN; c0 += 64) {
        __syncthreads();
        #pragma unroll
        for (int p = 0; p < 2; p++) {
            const int c = tid + p * 256;
            const int r = c >> 3, off = (c & 7) * 8;
            const size_t gi = (size_t)(c0 + r) * DMODEL + hoff + off;
            *(uint4*)&KHs[r * AP + off] = *(const uint4*)&Kh[gi];
            *(uint4*)&KLs[r * AP + off] = *(const uint4*)&Kl[gi];
            *(uint4*)&VHs[r * AP + off] = *(const uint4*)&Vh[gi];
            *(uint4*)&VLs[r * AP + off] = *(const uint4*)&Vl[gi];
        }
        __syncthreads();

        // ---- S = Q K^T ----
        float SP[8][4];
        #pragma unroll
        for (int a = 0; a < 8; a++)
            #pragma unroll
            for (int b = 0; b < 4; b++) SP[a][b] = 0.f;

        #pragma unroll
        for (int kk = 0; kk < 4; kk++) {
            unsigned qh4[4], ql4[4];
            const int qrow = m0 + (li & 1) * 8 + lj;
            const int qcol = kk * 16 + (li >> 1) * 8;
            LDSM4(qh4, saddr(&QHs[qrow * AP + qcol]));
            LDSM4(ql4, saddr(&QLs[qrow * AP + qcol]));
            #pragma unroll
            for (int ntp = 0; ntp < 4; ntp++) {
                const int krow = ntp * 16 + (li >> 1) * 8 + lj;
                const int kcol = kk * 16 + (li & 1) * 8;
                unsigned bh[4], bl[4];
                LDSM4(bh, saddr(&KHs[krow * AP + kcol]));
                LDSM4(bl, saddr(&KLs[krow * AP + kcol]));
                MMA_BF16(SP[2 * ntp],     qh4, bh[0], bh[1]);
                MMA_BF16(SP[2 * ntp],     ql4, bh[0], bh[1]);
                MMA_BF16(SP[2 * ntp],     qh4, bl[0], bl[1]);
                MMA_BF16(SP[2 * ntp + 1], qh4, bh[2], bh[3]);
                MMA_BF16(SP[2 * ntp + 1], ql4, bh[2], bh[3]);
                MMA_BF16(SP[2 * ntp + 1], qh4, bl[2], bl[3]);
            }
        }

        // ---- online softmax (rows g and g+8) ----
        float mx0 = -1e30f, mx1 = -1e30f;
        #pragma unroll
        for (int nt = 0; nt < 8; nt++) {
            mx0 = fmaxf(mx0, fmaxf(SP[nt][0], SP[nt][1]));
            mx1 = fmaxf(mx1, fmaxf(SP[nt][2], SP[nt][3]));
        }
        mx0 = fmaxf(mx0, __shfl_xor_sync(0xffffffffu, mx0, 1));
        mx0 = fmaxf(mx0, __shfl_xor_sync(0xffffffffu, mx0, 2));
        mx1 = fmaxf(mx1, __shfl_xor_sync(0xffffffffu, mx1, 1));
        mx1 = fmaxf(mx1, __shfl_xor_sync(0xffffffffu, mx1, 2));

        const float mn0 = fmaxf(mrow0, mx0 * C1);
        const float mn1 = fmaxf(mrow1, mx1 * C1);
        const float cor0 = __expf(mrow0 - mn0);
        const float cor1 = __expf(mrow1 - mn1);
        mrow0 = mn0; mrow1 = mn1;

        float rs0 = 0.f, rs1 = 0.f;
        #pragma unroll
        for (int nt = 0; nt < 8; nt++) {
            SP[nt][0] = __expf(fmaf(SP[nt][0], C1, -mn0)); rs0 += SP[nt][0];
            SP[nt][1] = __expf(fmaf(SP[nt][1], C1, -mn0)); rs0 += SP[nt][1];
            SP[nt][2] = __expf(fmaf(SP[nt][2], C1, -mn1)); rs1 += SP[nt][2];
            SP[nt][3] = __expf(fmaf(SP[nt][3], C1, -mn1)); rs1 += SP[nt][3];
        }
        rs0 += __shfl_xor_sync(0xffffffffu, rs0, 1);
        rs0 += __shfl_xor_sync(0xffffffffu, rs0, 2);
        rs1 += __shfl_xor_sync(0xffffffffu, rs1, 1);
        rs1 += __shfl_xor_sync(0xffffffffu, rs1, 2);
        lrow0 = lrow0 * cor0 + rs0;
        lrow1 = lrow1 * cor1 + rs1;
        #pragma unroll
        for (int nt = 0; nt < 8; nt++) {
            Oa[nt][0] *= cor0; Oa[nt][1] *= cor0;
            Oa[nt][2] *= cor1; Oa[nt][3] *= cor1;
        }

        // ---- O += P V  (P frags built from S c-frags; V via ldmatrix.trans) ----
        #pragma unroll
        for (int kk = 0; kk < 4; kk++) {
            unsigned aph[4], apl[4];
            split_pack(SP[2 * kk][0],     SP[2 * kk][1],     aph[0], apl[0]);
            split_pack(SP[2 * kk][2],     SP[2 * kk][3],     aph[1], apl[1]);
            split_pack(SP[2 * kk + 1][0], SP[2 * kk + 1][1], aph[2], apl[2]);
            split_pack(SP[2 * kk + 1][2], SP[2 * kk + 1][3], aph[3], apl[3]);
            #pragma unroll
            for (int ntp = 0; ntp < 4; ntp++) {
                const int vrow = kk * 16 + (li & 1) * 8 + lj;
                const int vcol = ntp * 16 + (li >> 1) * 8;
                unsigned bh[4], bl[4];
                LDSM4T(bh, saddr(&VHs[vrow * AP + vcol]));
                LDSM4T(bl, saddr(&VLs[vrow * AP + vcol]));
                MMA_BF16(Oa[2 * ntp],     aph, bh[0], bh[1]);
                MMA_BF16(Oa[2 * ntp],     apl, bh[0], bh[1]);
                MMA_BF16(Oa[2 * ntp],     aph, bl[0], bl[1]);
                MMA_BF16(Oa[2 * ntp + 1], aph, bh[2], bh[3]);
                MMA_BF16(Oa[2 * ntp + 1], apl, bh[2], bh[3]);
                MMA_BF16(Oa[2 * ntp + 1], aph, bl[2], bl[3]);
            }
        }
    }

    // ---- epilogue: normalize, split to hi/lo bf16 ----
    const float il0 = 1.f / lrow0;
    const float il1 = 1.f / lrow1;
    const int r0 = qBase + m0 + g;
    #pragma unroll
    for (int nt = 0; nt < 8; nt++) {
        const int c = hoff + nt * 8 + 2 * t;
        store_split(Ch, Cl, (size_t)r0 * DMODEL + c,       Oa[nt][0] * il0, Oa[nt][1] * il0);
        store_split(Ch, Cl, (size_t)(r0 + 8) * DMODEL + c, Oa[nt][2] * il1, Oa[nt][3] * il1);
    }
}

// ---------------------------------------------------------------------------
extern "C" void kernel_launch(void* const* d_in, const int* in_sizes, int n_in,
                              void* d_out, int out_size)
{
    const float* q  = (const float*)d_in[0];
    const float* k  = (const float*)d_in[1];
    const float* v  = (const float*)d_in[2];
    const float* Wq = (const float*)d_in[3];
    const float* bq = (const float*)d_in[4];
    const float* Wk = (const float*)d_in[5];
    const float* bk = (const float*)d_in[6];
    const float* Wv = (const float*)d_in[7];
    const float* bv = (const float*)d_in[8];
    const float* Wo = (const float*)d_in[9];
    const float* bo = (const float*)d_in[10];
    float* out = (float*)d_out;

    bf16* B;
    cudaGetSymbolAddress((void**)&B, g_buf);
    const size_t SDn = (size_t)S_LEN * DMODEL;
    const size_t DDn = (size_t)DMODEL * DMODEL;
    bf16 *iqh = B,           *iql = B + SDn;
    bf16 *ikh = B + 2 * SDn, *ikl = B + 3 * SDn;
    bf16 *ivh = B + 4 * SDn, *ivl = B + 5 * SDn;
    bf16* W0 = B + 6 * SDn;
    bf16 *wqh = W0,           *wql = W0 + DDn;
    bf16 *wkh = W0 + 2 * DDn, *wkl = W0 + 3 * DDn;
    bf16 *wvh = W0 + 4 * DDn, *wvl = W0 + 5 * DDn;
    bf16 *woh = W0 + 6 * DDn, *wol = W0 + 7 * DDn;
    bf16* P0 = W0 + 8 * DDn;
    bf16 *Qh = P0,           *Ql = P0 + SDn;
    bf16 *Kh = P0 + 2 * SDn, *Kl = P0 + 3 * SDn;
    bf16 *Vh = P0 + 4 * SDn, *Vl = P0 + 5 * SDn;
    bf16 *Cph = P0 + 6 * SDn, *Cpl = P0 + 7 * SDn;

    cudaFuncSetAttribute(gemm_bf16_split, cudaFuncAttributeMaxDynamicSharedMemorySize, 49152);
    cudaFuncSetAttribute(attn_bf16_split, cudaFuncAttributeMaxDynamicSharedMemorySize, 73728);

    const int T = 256;
    split_f32_kernel<<<(int)(SDn / 4 / T), T>>>(q, iqh, iql, (int)(SDn / 4));
    split_f32_kernel<<<(int)(SDn / 4 / T), T>>>(k, ikh, ikl, (int)(SDn / 4));
    split_f32_kernel<<<(int)(SDn / 4 / T), T>>>(v, ivh, ivl, (int)(SDn / 4));
    split_f32_kernel<<<(int)(DDn / 4 / T), T>>>(Wq, wqh, wql, (int)(DDn / 4));
    split_f32_kernel<<<(int)(DDn / 4 / T), T>>>(Wk, wkh, wkl, (int)(DDn / 4));
    split_f32_kernel<<<(int)(DDn / 4 / T), T>>>(Wv, wvh, wvl, (int)(DDn / 4));
    split_f32_kernel<<<(int)(DDn / 4 / T), T>>>(Wo, woh, wol, (int)(DDn / 4));

    dim3 gg(DMODEL / 128, S_LEN / 128);   // (8, 32)
    gemm_bf16_split<<<gg, 256, 49152>>>(iqh, iql, wqh, wql, bq, nullptr, Qh, Ql, S_LEN, DMODEL, DMODEL);
    gemm_bf16_split<<<gg, 256, 49152>>>(ikh, ikl, wkh, wkl, bk, nullptr, Kh, Kl, S_LEN, DMODEL, DMODEL);
    gemm_bf16_split<<<gg, 256, 49152>>>(ivh, ivl, wvh, wvl, bv, nullptr, Vh, Vl, S_LEN, DMODEL, DMODEL);

    dim3 ga(S_LEN / 128, NHEAD);          // (32, 16)
    attn_bf16_split<<<ga, 256, 73728>>>(Qh, Ql, Kh, Kl, Vh, Vl, Cph, Cpl);

    gemm_bf16_split<<<gg, 256, 49152>>>(Cph, Cpl, woh, wol, bo, out, nullptr, nullptr, S_LEN, DMODEL, DMODEL);
}